// round 1
// baseline (speedup 1.0000x reference)
#include <cuda_runtime.h>
#include <cuda_bf16.h>

// Problem constants (fixed shapes from setup_inputs)
#define BDIM   8
#define SDIM   4096
#define HDIM   16
#define PDIM   64
#define NDIM   64
#define LCHUNK 64
#define NCHUNK 64          // SDIM / LCHUNK
#define NBH    (BDIM * HDIM)   // 128
#define THRESH 40.0f       // skip chunks with max log-weight < -THRESH (exp(-40)=4e-18)

// Scratch (allocation-free rule: __device__ globals)
__device__ float g_w[NBH * SDIM];   // per-timestep decay weight exp(S_total - S(t))
__device__ int   g_start[NBH];      // first active chunk per (b,h)

// ---------------------------------------------------------------------------
// Prep kernel: per (b,h) compute chunk totals, suffix sums, per-t weights,
// and the first chunk whose contribution is non-negligible.
// Grid: NBH blocks x NCHUNK threads (thread j owns chunk j).
// ---------------------------------------------------------------------------
__global__ void prep_kernel(const float* __restrict__ A) {
    const int bh = blockIdx.x;
    const int b  = bh >> 4;
    const int h  = bh & 15;
    const int j  = threadIdx.x;          // chunk index 0..63

    __shared__ float Tj[NCHUNK];         // per-chunk sum of A (negative)
    __shared__ float Uj[NCHUNK];         // suffix sum of chunks AFTER j (negative)
    __shared__ int   s_start;

    const float* Ab = A + (long)b * SDIM * HDIM + h;   // A[b, t, h], stride HDIM in t
    const int t0 = j * LCHUNK;

    // Pass 1: chunk total
    float tot = 0.0f;
    #pragma unroll 8
    for (int i = 0; i < LCHUNK; i++) tot += Ab[(t0 + i) * HDIM];
    Tj[j] = tot;
    __syncthreads();

    // Suffix scan + active-start detection (serial over 64, trivial cost)
    if (j == 0) {
        float suf = 0.0f;
        int start = NCHUNK - 1;
        for (int k = NCHUNK - 1; k >= 0; k--) {
            Uj[k] = suf;                 // sum of totals of chunks > k
            if (suf > -THRESH) start = k;
            suf += Tj[k];
        }
        s_start = start;
        g_start[bh] = start;
    }
    __syncthreads();

    // Pass 2: per-timestep weights for active chunks
    if (j >= s_start) {
        const float base = Uj[j] + Tj[j];   // suffix incl. rest of this chunk
        float cs = 0.0f;
        float* wout = g_w + bh * SDIM + t0;
        #pragma unroll 8
        for (int i = 0; i < LCHUNK; i++) {
            cs += Ab[(t0 + i) * HDIM];
            wout[i] = expf(base - cs);      // exp(S_total - S(t)), accurate expf
        }
    }
}

// ---------------------------------------------------------------------------
// Main kernel: one block per (b,h). Accumulate out[p,n] += w_t * X[t,p]*B[t,n]
// over active chunks. 256 threads, 4x4 register tile per thread.
// Register-staged pipeline: issue next chunk's global loads before compute.
// ---------------------------------------------------------------------------
__global__ void __launch_bounds__(256, 1)
mamba_state_kernel(const float* __restrict__ X,
                   const float* __restrict__ B,
                   float* __restrict__ out) {
    __shared__ float4 xs[LCHUNK][16];    // w-scaled X tile, 64 rows x 16 float4
    __shared__ float4 bs[LCHUNK][16];    // B tile

    const int bh  = blockIdx.x;
    const int b   = bh >> 4;
    const int h   = bh & 15;
    const int tid = threadIdx.x;
    const int tp  = tid >> 4;            // 0..15: p-block (and load row group)
    const int tn  = tid & 15;            // 0..15: n-block (and load col float4)

    const int j0 = g_start[bh];

    const float4* X4 = (const float4*)X; // row t at ((b*S+t)*H + h)*16 float4s
    const float4* B4 = (const float4*)B;
    const float*  wrow = g_w + bh * SDIM;

    float acc[4][4];
    #pragma unroll
    for (int i = 0; i < 4; i++)
        #pragma unroll
        for (int k = 0; k < 4; k++) acc[i][k] = 0.0f;

    float4 xr[4], br[4];
    float  wr[4];

    // Preload chunk j0
    {
        const int t0 = j0 * LCHUNK;
        #pragma unroll
        for (int k = 0; k < 4; k++) {
            const int t = t0 + tp + 16 * k;
            const int base = ((b * SDIM + t) * HDIM + h) * 16 + tn;
            xr[k] = X4[base];
            br[k] = B4[base];
            wr[k] = wrow[t];
        }
    }

    for (int j = j0; j < NCHUNK; j++) {
        // Stage registers -> shared (scale X by decay weight at store time)
        #pragma unroll
        for (int k = 0; k < 4; k++) {
            const int r = tp + 16 * k;
            float4 xv = xr[k];
            const float w = wr[k];
            xv.x *= w; xv.y *= w; xv.z *= w; xv.w *= w;
            xs[r][tn] = xv;
            bs[r][tn] = br[k];
        }
        __syncthreads();

        // Issue next chunk's loads now; latency hides behind compute below
        if (j + 1 < NCHUNK) {
            const int t0 = (j + 1) * LCHUNK;
            #pragma unroll
            for (int k = 0; k < 4; k++) {
                const int t = t0 + tp + 16 * k;
                const int base = ((b * SDIM + t) * HDIM + h) * 16 + tn;
                xr[k] = X4[base];
                br[k] = B4[base];
                wr[k] = wrow[t];
            }
        }

        // Rank-64 update: acc[4x4] += xs[l][tp] (outer) bs[l][tn]
        #pragma unroll 4
        for (int l = 0; l < LCHUNK; l++) {
            const float4 xv = xs[l][tp];   // broadcast within half-warp
            const float4 bv = bs[l][tn];   // conflict-free in .128 subphases
            acc[0][0] += xv.x * bv.x; acc[0][1] += xv.x * bv.y;
            acc[0][2] += xv.x * bv.z; acc[0][3] += xv.x * bv.w;
            acc[1][0] += xv.y * bv.x; acc[1][1] += xv.y * bv.y;
            acc[1][2] += xv.y * bv.z; acc[1][3] += xv.y * bv.w;
            acc[2][0] += xv.z * bv.x; acc[2][1] += xv.z * bv.y;
            acc[2][2] += xv.z * bv.z; acc[2][3] += xv.z * bv.w;
            acc[3][0] += xv.w * bv.x; acc[3][1] += xv.w * bv.y;
            acc[3][2] += xv.w * bv.z; acc[3][3] += xv.w * bv.w;
        }
        __syncthreads();
    }

    // Write out[b,h,p,n]: p = 4*tp+i, n-block tn (float4 along n)
    float4* out4 = (float4*)out + (long)bh * PDIM * 16;
    #pragma unroll
    for (int i = 0; i < 4; i++) {
        const int p = 4 * tp + i;
        float4 v;
        v.x = acc[i][0]; v.y = acc[i][1]; v.z = acc[i][2]; v.w = acc[i][3];
        out4[p * 16 + tn] = v;
    }
}

// ---------------------------------------------------------------------------
extern "C" void kernel_launch(void* const* d_in, const int* in_sizes, int n_in,
                              void* d_out, int out_size) {
    const float* X = (const float*)d_in[0];
    const float* A = (const float*)d_in[1];
    const float* B = (const float*)d_in[2];
    float* out = (float*)d_out;

    prep_kernel<<<NBH, NCHUNK>>>(A);
    mamba_state_kernel<<<NBH, 256>>>(X, B, out);
}

// round 2
// speedup vs baseline: 1.1231x; 1.1231x over previous
#include <cuda_runtime.h>
#include <cuda_bf16.h>

// Problem constants (fixed shapes from setup_inputs)
#define BDIM   8
#define SDIM   4096
#define HDIM   16
#define PDIM   64
#define NDIM   64
#define LCHUNK 64
#define NCHUNK 64
#define NBH    (BDIM * HDIM)   // 128
#define SPLIT  4               // chunk-parallel blocks per (b,h)
#define THRESH 40.0f           // skip chunks with max log-weight < -THRESH

// Scratch (allocation-free rule: __device__ globals)
__device__ float g_w[NBH * SDIM];                      // per-t decay weights
__device__ int   g_start[NBH];                         // first active chunk
__device__ float g_part[SPLIT * NBH * PDIM * NDIM];    // split partial sums (8MB)

// ---------------------------------------------------------------------------
// Packed-f32 FMA helpers (sm_100+ PTX: fma.rn.f32x2)
// ---------------------------------------------------------------------------
__device__ __forceinline__ void ffma2(unsigned long long& d,
                                      unsigned long long a,
                                      unsigned long long b) {
    asm("fma.rn.f32x2 %0, %1, %2, %0;" : "+l"(d) : "l"(a), "l"(b));
}
__device__ __forceinline__ unsigned long long pack2(float lo, float hi) {
    unsigned long long r;
    asm("mov.b64 %0, {%1, %2};" : "=l"(r) : "f"(lo), "f"(hi));
    return r;
}
__device__ __forceinline__ void unpack2(unsigned long long v, float& lo, float& hi) {
    asm("mov.b64 {%0, %1}, %2;" : "=f"(lo), "=f"(hi) : "l"(v));
}

// ---------------------------------------------------------------------------
// Prep: per (b,h) chunk totals, suffix sums, per-t weights, active start.
// ---------------------------------------------------------------------------
__global__ void prep_kernel(const float* __restrict__ A) {
    const int bh = blockIdx.x;
    const int b  = bh >> 4;
    const int h  = bh & 15;
    const int j  = threadIdx.x;          // chunk 0..63

    __shared__ float Tj[NCHUNK];
    __shared__ float Uj[NCHUNK];
    __shared__ int   s_start;

    const float* Ab = A + (long)b * SDIM * HDIM + h;
    const int t0 = j * LCHUNK;

    float tot = 0.0f;
    #pragma unroll 8
    for (int i = 0; i < LCHUNK; i++) tot += Ab[(t0 + i) * HDIM];
    Tj[j] = tot;
    __syncthreads();

    if (j == 0) {
        float suf = 0.0f;
        int start = NCHUNK - 1;
        for (int k = NCHUNK - 1; k >= 0; k--) {
            Uj[k] = suf;
            if (suf > -THRESH) start = k;
            suf += Tj[k];
        }
        s_start = start;
        g_start[bh] = start;
    }
    __syncthreads();

    if (j >= s_start) {
        const float base = Uj[j] + Tj[j];
        float cs = 0.0f;
        float* wout = g_w + bh * SDIM + t0;
        #pragma unroll 8
        for (int i = 0; i < LCHUNK; i++) {
            cs += Ab[(t0 + i) * HDIM];
            wout[i] = expf(base - cs);
        }
    }
}

// ---------------------------------------------------------------------------
// Main: grid (NBH, SPLIT). Block (bh,k) handles chunks j0+k, j0+k+SPLIT, ...
// 256 threads, 4x4 output tile per thread via packed FFMA2.
// ---------------------------------------------------------------------------
__global__ void __launch_bounds__(256)
mamba_state_kernel(const float* __restrict__ X,
                   const float* __restrict__ B,
                   float* __restrict__ part) {
    __shared__ float4 xs[LCHUNK][16];    // w-scaled X tile
    __shared__ float4 bs[LCHUNK][16];    // B tile

    const int bh  = blockIdx.x;
    const int k0  = blockIdx.y;          // split index
    const int b   = bh >> 4;
    const int h   = bh & 15;
    const int tid = threadIdx.x;
    const int tp  = tid >> 4;            // 0..15
    const int tn  = tid & 15;            // 0..15

    const int j0 = g_start[bh];

    const float4* X4 = (const float4*)X;
    const float4* B4 = (const float4*)B;
    const float*  wrow = g_w + bh * SDIM;

    unsigned long long acc2[4][2];
    #pragma unroll
    for (int i = 0; i < 4; i++) { acc2[i][0] = 0ull; acc2[i][1] = 0ull; }

    float4 xr[4], br[4];
    float  wr[4];

    int j = j0 + k0;
    if (j < NCHUNK) {
        const int t0 = j * LCHUNK;
        #pragma unroll
        for (int q = 0; q < 4; q++) {
            const int t = t0 + tp + 16 * q;
            const int base = ((b * SDIM + t) * HDIM + h) * 16 + tn;
            xr[q] = X4[base];
            br[q] = B4[base];
            wr[q] = wrow[t];
        }
    }

    for (; j < NCHUNK; j += SPLIT) {
        // Stage regs -> shared (scale X by weight at store)
        #pragma unroll
        for (int q = 0; q < 4; q++) {
            const int r = tp + 16 * q;
            float4 xv = xr[q];
            const float w = wr[q];
            xv.x *= w; xv.y *= w; xv.z *= w; xv.w *= w;
            xs[r][tn] = xv;
            bs[r][tn] = br[q];
        }
        __syncthreads();

        // Prefetch next assigned chunk
        if (j + SPLIT < NCHUNK) {
            const int t0 = (j + SPLIT) * LCHUNK;
            #pragma unroll
            for (int q = 0; q < 4; q++) {
                const int t = t0 + tp + 16 * q;
                const int base = ((b * SDIM + t) * HDIM + h) * 16 + tn;
                xr[q] = X4[base];
                br[q] = B4[base];
                wr[q] = wrow[t];
            }
        }

        // Rank-64 update with packed FFMA2
        #pragma unroll 4
        for (int l = 0; l < LCHUNK; l++) {
            const float4 xv = xs[l][tp];
            const float4 bv = bs[l][tn];
            const unsigned long long blo = pack2(bv.x, bv.y);
            const unsigned long long bhi = pack2(bv.z, bv.w);
            const unsigned long long x0 = pack2(xv.x, xv.x);
            const unsigned long long x1 = pack2(xv.y, xv.y);
            const unsigned long long x2 = pack2(xv.z, xv.z);
            const unsigned long long x3 = pack2(xv.w, xv.w);
            ffma2(acc2[0][0], x0, blo); ffma2(acc2[0][1], x0, bhi);
            ffma2(acc2[1][0], x1, blo); ffma2(acc2[1][1], x1, bhi);
            ffma2(acc2[2][0], x2, blo); ffma2(acc2[2][1], x2, bhi);
            ffma2(acc2[3][0], x3, blo); ffma2(acc2[3][1], x3, bhi);
        }
        __syncthreads();
    }

    // Write partials: part[k0][bh][p][n]
    float4* out4 = (float4*)part + ((long)k0 * NBH + bh) * PDIM * 16;
    #pragma unroll
    for (int i = 0; i < 4; i++) {
        const int p = 4 * tp + i;
        float4 v;
        unpack2(acc2[i][0], v.x, v.y);
        unpack2(acc2[i][1], v.z, v.w);
        out4[p * 16 + tn] = v;
    }
}

// ---------------------------------------------------------------------------
// Reduce: out = sum over SPLIT partials. Deterministic.
// ---------------------------------------------------------------------------
__global__ void reduce_kernel(const float* __restrict__ part,
                              float* __restrict__ out) {
    const int i = blockIdx.x * 256 + threadIdx.x;     // float4 index
    const int STRIDE = NBH * PDIM * NDIM / 4;         // 131072
    const float4* p4 = (const float4*)part;
    float4 a = p4[i];
    float4 b = p4[i + STRIDE];
    float4 c = p4[i + 2 * STRIDE];
    float4 d = p4[i + 3 * STRIDE];
    float4 s;
    s.x = (a.x + b.x) + (c.x + d.x);
    s.y = (a.y + b.y) + (c.y + d.y);
    s.z = (a.z + b.z) + (c.z + d.z);
    s.w = (a.w + b.w) + (c.w + d.w);
    ((float4*)out)[i] = s;
}

// ---------------------------------------------------------------------------
extern "C" void kernel_launch(void* const* d_in, const int* in_sizes, int n_in,
                              void* d_out, int out_size) {
    const float* X = (const float*)d_in[0];
    const float* A = (const float*)d_in[1];
    const float* B = (const float*)d_in[2];
    float* out = (float*)d_out;

    float* part;
    cudaGetSymbolAddress((void**)&part, g_part);

    prep_kernel<<<NBH, NCHUNK>>>(A);
    dim3 grid(NBH, SPLIT);
    mamba_state_kernel<<<grid, 256>>>(X, B, part);
    reduce_kernel<<<NBH * PDIM * NDIM / 4 / 256, 256>>>(part, out);
}